// round 8
// baseline (speedup 1.0000x reference)
#include <cuda_runtime.h>
#include <cuda_bf16.h>

// Problem constants: LX=8, LY=4, D=4, PHYS=2, batch=128
#define NB   128
#define NCOL 16384

// Scratch: correction matrix in bf16 (halves store/load/writeback traffic)
__device__ __align__(16) __nv_bfloat16 g_Cb[NB * NCOL];

// f32x2 packed helpers (sm_100+ PTX)
#define FMA2(d, a, b) asm("fma.rn.f32x2 %0, %1, %2, %0;" : "+l"(d) : "l"(a), "l"(b))
#define PACK2(d, lo, hi) asm("mov.b64 %0, {%1, %2};" : "=l"(d) : "f"(lo), "f"(hi))
#define UNPACK2(lo, hi, s) asm("mov.b64 {%0, %1}, %2;" : "=f"(lo), "=f"(hi) : "l"(s))

// ---------------------------------------------------------------------------
// Kernel 1 (fused hidden + gemm): grid (32, 8) = 256 blocks, 2/SM.
//   H[b,k] = relu(b1[k] + cfg[b,:]·W1[:,k])
//   C[b,n] = 0.001 * (b2[n] + H[b,:]·W2[:,n])      (stored bf16)
// Thread: 1 column x 16 batches (8 f32x2 accumulators).
// ---------------------------------------------------------------------------
__global__ void __launch_bounds__(512, 2)
k_gemm(const int* __restrict__ cfg,
       const float* __restrict__ W1,
       const float* __restrict__ b1,
       const float* __restrict__ W2,
       const float* __restrict__ b2) {
    __shared__ __align__(16) float Hs[64 * 16];   // [hidden k][batch]
    __shared__ int cs[16 * 32];                    // [batch][cfg k]

    const int tid = threadIdx.x;
    const int n   = blockIdx.x * 512 + tid;
    const int b0  = blockIdx.y * 16;

    cs[tid] = cfg[b0 * 32 + tid];
    __syncthreads();

    // hidden: thread owns hidden index j, batches bl and bl+8
    {
        const int j  = tid & 63;
        const int bl = tid >> 6;          // 0..7
        float w1c[32];
#pragma unroll
        for (int k = 0; k < 32; k++) w1c[k] = W1[k * 64 + j];
        const float bj = b1[j];
        float acc0 = bj, acc1 = bj;
#pragma unroll
        for (int k = 0; k < 32; k++) {
            acc0 = fmaf((float)cs[bl * 32 + k],       w1c[k], acc0);
            acc1 = fmaf((float)cs[(bl + 8) * 32 + k], w1c[k], acc1);
        }
        Hs[j * 16 + bl]     = fmaxf(acc0, 0.0f);
        Hs[j * 16 + bl + 8] = fmaxf(acc1, 0.0f);
    }
    __syncthreads();

    unsigned long long acc[8];
    {
        const float bias = b2[n];
        unsigned long long z;
        PACK2(z, bias, bias);
#pragma unroll
        for (int p = 0; p < 8; p++) acc[p] = z;
    }

#pragma unroll 8
    for (int k = 0; k < 64; k++) {
        const float w = W2[k * NCOL + n];
        unsigned long long wp;
        PACK2(wp, w, w);
        const ulonglong2* hp = (const ulonglong2*)(Hs + k * 16);
#pragma unroll
        for (int q = 0; q < 4; q++) {
            ulonglong2 hh = hp[q];               // batches 4q..4q+3 (broadcast)
            FMA2(acc[2 * q],     hh.x, wp);
            FMA2(acc[2 * q + 1], hh.y, wp);
        }
    }

#pragma unroll
    for (int p = 0; p < 8; p++) {
        float lo, hi;
        UNPACK2(lo, hi, acc[p]);
        g_Cb[(b0 + 2 * p)     * NCOL + n] = __float2bfloat16(0.001f * lo);
        g_Cb[(b0 + 2 * p + 1) * NCOL + n] = __float2bfloat16(0.001f * hi);
    }
}

// ---------------------------------------------------------------------------
// Kernel 2: per-batch assembly + SPLIT transfer-matrix chain. 512 threads.
//
// u-quad layouts, row stride 76 floats (16B-aligned, minimal conflicts):
//   BF[x][r=j][s=i][U]  (forward bot:  read bot_u[s,r] along s, float4 over u)
//   BA[x][r=i][s=j][U]  (adjoint bot)
//   TF[x][J=j][I2=i][d] (forward top:  read top_u[I2,J])
//   TA[x][J=i][I2=j][d] (adjoint top)
// Phase 1: 4 STS.128 per x per thread; builds for x-group h = t>>8.
// Phase 2 (threads 0-255, two 128-thread named-barrier groups):
//   P_u[r,I]  = sum_s bot_u[s,r]·V[s,I]     (FFMA2, ulonglong2 operands)
//   V'[r,J]   = sum_u sum_I2 P_u[r,I2]·top_u[I2,J]
// Final: dot of the two half-chain results.
// ---------------------------------------------------------------------------
#define XSTR 76
#define XAR  1216          // 16*76 floats per x per layout

#define SM_S    0          // 8192
#define SM_BF   8192       // 8*1216 = 9728
#define SM_TF   17920      // 9728
#define SM_BA   27648      // 9728
#define SM_TA   37376      // 9728
#define SM_P    47104      // 2*1216
#define SM_V    49536      // 2*2*320
#define SM_VF   50816      // 512
#define SM_RED  51328      // 16
#define SM_CFG  51344      // 32 ints
#define SMEM_CH (51376 * 4)

__global__ void __launch_bounds__(512, 1)
k_chain(const int* __restrict__ cfg,
        const float* __restrict__ A,
        float* __restrict__ out) {
    extern __shared__ __align__(16) float sm[];
    int* c = (int*)(sm + SM_CFG);

    const int b = blockIdx.x;
    const int t = threadIdx.x;

    if (t < 32) c[t] = cfg[b * 32 + t];
    __syncthreads();

    const __nv_bfloat16* Crow = g_Cb + b * NCOL;
    const int p = t & 255;
    const int h = t >> 8;            // x-group: h=0 -> x 0..3, h=1 -> x 4..7

    // ---------------- Phase 1: stage s (group's 4 x), build arenas ----------------
    {
        float g[16];
#pragma unroll
        for (int q = 0; q < 16; q++) {
            const int x = h * 4 + (q >> 2), y = q & 3;
            g[q] = A[x * 2048 + y * 512 + p * 2 + c[x * 4 + y]];
        }
#pragma unroll
        for (int q = 0; q < 16; q++) {
            const int x = h * 4 + (q >> 2), y = q & 3;
            sm[SM_S + x * 1024 + y * 256 + p] = g[q];
        }
    }
    __syncthreads();

    {
        const int i = p >> 4, j = p & 15;
        const int l = i >> 2, L = i & 3, r = j >> 2, R = j & 3;

        // prefetch this group's 4 x-sites' bf16 corrections (MLP-8)
        uint2 rcb[4], rct[4];
#pragma unroll
        for (int q = 0; q < 4; q++) {
            const int x = h * 4 + q;
            rcb[q] = *(const uint2*)(Crow + x * 1024 + p * 4);
            rct[q] = *(const uint2*)(Crow + 8192 + x * 1024 + p * 4);
        }

#pragma unroll
        for (int q = 0; q < 4; q++) {
            const int x = h * 4 + q;
            const float* sb = sm + SM_S + x * 1024;

            float2 cb01 = __bfloat1622float2(*(__nv_bfloat162*)&rcb[q].x);
            float2 cb23 = __bfloat1622float2(*(__nv_bfloat162*)&rcb[q].y);
            float2 ct01 = __bfloat1622float2(*(__nv_bfloat162*)&rct[q].x);
            float2 ct23 = __bfloat1622float2(*(__nv_bfloat162*)&rct[q].y);
            const float cbv[4] = {cb01.x, cb01.y, cb23.x, cb23.y};
            const float ctv[4] = {ct01.x, ct01.y, ct23.x, ct23.y};

            float r0v[4], r3v[4];
#pragma unroll
            for (int u = 0; u < 4; u++) {
                r0v[u] = sb[l * 64 + r * 16 + u];               // s0[l,r,0,u]
                r3v[u] = sb[768 + L * 64 + R * 16 + u * 4];     // s3[L,R,u,0]
            }
            float4 b4, t4;
            {
                float v[4];
#pragma unroll
                for (int U = 0; U < 4; U++) {
                    float a0 = 0.0f;
#pragma unroll
                    for (int u = 0; u < 4; u++)
                        a0 = fmaf(r0v[u], sb[256 + L * 64 + R * 16 + u * 4 + U], a0);
                    v[U] = a0 + cbv[U];
                }
                b4 = make_float4(v[0], v[1], v[2], v[3]);
            }
            {
                float v[4];
#pragma unroll
                for (int d = 0; d < 4; d++) {
                    float a0 = 0.0f;
#pragma unroll
                    for (int u = 0; u < 4; u++)
                        a0 = fmaf(sb[512 + l * 64 + r * 16 + d * 4 + u], r3v[u], a0);
                    v[d] = a0 + ctv[d];
                }
                t4 = make_float4(v[0], v[1], v[2], v[3]);
            }
            *(float4*)(sm + SM_BF + x * XAR + j * XSTR + i * 4) = b4;
            *(float4*)(sm + SM_BA + x * XAR + i * XSTR + j * 4) = b4;
            *(float4*)(sm + SM_TF + x * XAR + j * XSTR + i * 4) = t4;
            *(float4*)(sm + SM_TA + x * XAR + i * XSTR + j * 4) = t4;
        }
    }
    __syncthreads();   // arenas visible to phase 2

    // ---------------- Phase 2: two half-chains (threads 0-255) ----------------
    if (t < 256) {
        const int half = t >> 7;
        const int ht   = t & 127;
        const int I    = ht & 15;
        const int j2   = ht >> 4;             // owns rows j2, j2+8

        const float* botH = sm + (half ? SM_BA : SM_BF);
        const float* topH = sm + (half ? SM_TA : SM_TF);
        float* Ph = sm + SM_P + half * 1216;
        float* Vh = sm + SM_V + half * 640;
        const int barid = half + 1;

        for (int q = ht; q < 640; q += 128)
            Vh[q] = (q == 0) ? 1.0f : 0.0f;   // V[0,0]=1 in buffer 0
        asm volatile("bar.sync %0, %1;" :: "r"(barid), "r"(128) : "memory");

        float a0 = 0.0f, a1 = 0.0f;

#pragma unroll
        for (int s4 = 0; s4 < 4; s4++) {
            const int x = half ? (7 - s4) : s4;
            const float* bx  = botH + x * XAR;
            const float* tx2 = topH + x * XAR;
            const float* Vin  = Vh + (s4 & 1) * 320;
            float*       Vout = Vh + ((s4 + 1) & 1) * 320;

            // vl2[s] = (V[s,I], V[s,I]) packed
            unsigned long long vl2[16];
#pragma unroll
            for (int q = 0; q < 4; q++) {
                float4 v4 = *(const float4*)(Vin + I * 20 + q * 4);
                PACK2(vl2[4 * q + 0], v4.x, v4.x);
                PACK2(vl2[4 * q + 1], v4.y, v4.y);
                PACK2(vl2[4 * q + 2], v4.z, v4.z);
                PACK2(vl2[4 * q + 3], v4.w, v4.w);
            }

            // P-stage: both owned rows
#pragma unroll
            for (int rr = 0; rr < 2; rr++) {
                const int rw = j2 + 8 * rr;
                unsigned long long accA = 0ull, accB = 0ull;  // u01, u23
                const ulonglong2* bp = (const ulonglong2*)(bx + rw * XSTR);
#pragma unroll
                for (int s = 0; s < 16; s++) {
                    ulonglong2 bq = bp[s];
                    FMA2(accA, bq.x, vl2[s]);
                    FMA2(accB, bq.y, vl2[s]);
                }
                ulonglong2 pw; pw.x = accA; pw.y = accB;
                *(ulonglong2*)(Ph + rw * XSTR + I * 4) = pw;
            }
            asm volatile("bar.sync %0, %1;" :: "r"(barid), "r"(128) : "memory");

            // V'-stage: out(r, J=I)
            unsigned long long a0p = 0ull, a1p = 0ull;
            const ulonglong2* tp  = (const ulonglong2*)(tx2 + I * XSTR);
            const ulonglong2* pa  = (const ulonglong2*)(Ph + j2 * XSTR);
            const ulonglong2* pb  = (const ulonglong2*)(Ph + (j2 + 8) * XSTR);
#pragma unroll
            for (int s = 0; s < 16; s++) {
                ulonglong2 tq = tp[s];
                ulonglong2 qa = pa[s];
                ulonglong2 qb = pb[s];
                FMA2(a0p, qa.x, tq.x);
                FMA2(a1p, qb.x, tq.x);
                FMA2(a0p, qa.y, tq.y);
                FMA2(a1p, qb.y, tq.y);
            }
            float x0, x1, y0, y1;
            UNPACK2(x0, x1, a0p);
            UNPACK2(y0, y1, a1p);
            const float acc0 = x0 + x1;
            const float acc1 = y0 + y1;
            Vout[I * 20 + j2]     = acc0;
            Vout[I * 20 + j2 + 8] = acc1;
            a0 = acc0; a1 = acc1;
            asm volatile("bar.sync %0, %1;" :: "r"(barid), "r"(128) : "memory");
        }

        float* VF = sm + SM_VF;
        VF[half * 256 + j2 * 16 + I]       = a0;
        VF[half * 256 + (j2 + 8) * 16 + I] = a1;
    }
    __syncthreads();

    // ---------------- combine: dot of the two half-results ----------------
    if (t < 256) {
        const float* VF = sm + SM_VF;
        float prod = VF[t] * VF[256 + t];
#pragma unroll
        for (int o = 16; o; o >>= 1)
            prod += __shfl_xor_sync(0xffffffffu, prod, o);
        if ((t & 31) == 0) sm[SM_RED + (t >> 5)] = prod;
    }
    __syncthreads();
    if (t < 8) {
        float v = sm[SM_RED + t];
        v += __shfl_xor_sync(0xffu, v, 4);
        v += __shfl_xor_sync(0xffu, v, 2);
        v += __shfl_xor_sync(0xffu, v, 1);
        if (t == 0) out[b] = v;
    }
}

// ---------------------------------------------------------------------------
extern "C" void kernel_launch(void* const* d_in, const int* in_sizes, int n_in,
                              void* d_out, int out_size) {
    const int*   cfg = (const int*)d_in[0];
    const float* A   = (const float*)d_in[1];
    const float* W1  = (const float*)d_in[2];
    const float* b1  = (const float*)d_in[3];
    const float* W2  = (const float*)d_in[4];
    const float* b2  = (const float*)d_in[5];
    float* out = (float*)d_out;

    cudaFuncSetAttribute(k_chain, cudaFuncAttributeMaxDynamicSharedMemorySize,
                         SMEM_CH);

    k_gemm<<<dim3(32, 8), 512>>>(cfg, W1, b1, W2, b2);
    k_chain<<<NB, 512, SMEM_CH>>>(cfg, A, out);
}

// round 12
// speedup vs baseline: 1.1484x; 1.1484x over previous
#include <cuda_runtime.h>
#include <cuda_bf16.h>

// Problem constants: LX=8, LY=4, D=4, PHYS=2, batch=128
#define NB   128
#define NCOL 16384

// Scratch: correction matrix in bf16
__device__ __align__(16) __nv_bfloat16 g_Cb[NB * NCOL];

// f32x2 packed helpers (sm_100+ PTX)
#define FMA2(d, a, b) asm("fma.rn.f32x2 %0, %1, %2, %0;" : "+l"(d) : "l"(a), "l"(b))
#define PACK2(d, lo, hi) asm("mov.b64 %0, {%1, %2};" : "=l"(d) : "f"(lo), "f"(hi))
#define UNPACK2(lo, hi, s) asm("mov.b64 {%0, %1}, %2;" : "=f"(lo), "=f"(hi) : "l"(s))

// ---------------------------------------------------------------------------
// Kernel 1 (fused hidden + gemm), R7 tiling: 512 thr, 2 cols x 16 batches.
//   H[b,k] = relu(b1[k] + cfg[b,:]·W1[:,k])
//   C[b,n] = 0.001 * (b2[n] + H[b,:]·W2[:,n])    (bf16, paired stores)
// grid (16, 8) = 128 blocks.
// ---------------------------------------------------------------------------
__global__ void __launch_bounds__(512, 1)
k_gemm(const int* __restrict__ cfg,
       const float* __restrict__ W1,
       const float* __restrict__ b1,
       const float* __restrict__ W2,
       const float* __restrict__ b2) {
    __shared__ __align__(16) float Hs[64 * 16];   // [hidden k][batch]
    __shared__ int cs[16 * 32];                    // [batch][cfg k]

    const int tid = threadIdx.x;
    const int n0  = blockIdx.x * 1024 + tid * 2;
    const int b0  = blockIdx.y * 16;

    cs[tid] = cfg[b0 * 32 + tid];
    __syncthreads();

    // hidden: thread owns hidden index j, batches bl and bl+8
    {
        const int j  = tid & 63;
        const int bl = tid >> 6;          // 0..7
        float w1c[32];
#pragma unroll
        for (int k = 0; k < 32; k++) w1c[k] = W1[k * 64 + j];
        const float bj = b1[j];
        float acc0 = bj, acc1 = bj;
#pragma unroll
        for (int k = 0; k < 32; k++) {
            acc0 = fmaf((float)cs[bl * 32 + k],       w1c[k], acc0);
            acc1 = fmaf((float)cs[(bl + 8) * 32 + k], w1c[k], acc1);
        }
        Hs[j * 16 + bl]     = fmaxf(acc0, 0.0f);
        Hs[j * 16 + bl + 8] = fmaxf(acc1, 0.0f);
    }
    __syncthreads();

    // GEMM: acc0 = col n0, acc1 = col n0+1; 8 batch-pairs each (f32x2)
    unsigned long long acc0[8], acc1[8];
    {
        const float2 bb = *(const float2*)(b2 + n0);
        unsigned long long z0, z1;
        PACK2(z0, bb.x, bb.x);
        PACK2(z1, bb.y, bb.y);
#pragma unroll
        for (int p = 0; p < 8; p++) { acc0[p] = z0; acc1[p] = z1; }
    }

#pragma unroll 8
    for (int k = 0; k < 64; k++) {
        const float2 w = *(const float2*)(W2 + k * NCOL + n0);
        unsigned long long w0p, w1p;
        PACK2(w0p, w.x, w.x);
        PACK2(w1p, w.y, w.y);
        const ulonglong2* hp = (const ulonglong2*)(Hs + k * 16);
#pragma unroll
        for (int q = 0; q < 4; q++) {
            ulonglong2 hh = hp[q];               // batches 4q..4q+3 (broadcast)
            FMA2(acc0[2 * q],     hh.x, w0p);
            FMA2(acc1[2 * q],     hh.x, w1p);
            FMA2(acc0[2 * q + 1], hh.y, w0p);
            FMA2(acc1[2 * q + 1], hh.y, w1p);
        }
    }

#pragma unroll
    for (int p = 0; p < 8; p++) {
        float l0, h0, l1, h1;
        UNPACK2(l0, h0, acc0[p]);
        UNPACK2(l1, h1, acc1[p]);
        *(__nv_bfloat162*)(g_Cb + (b0 + 2 * p)     * NCOL + n0) =
            __floats2bfloat162_rn(0.001f * l0, 0.001f * l1);
        *(__nv_bfloat162*)(g_Cb + (b0 + 2 * p + 1) * NCOL + n0) =
            __floats2bfloat162_rn(0.001f * h0, 0.001f * h1);
    }
}

// ---------------------------------------------------------------------------
// Kernel 2: per-batch assembly + split chain, two DECOUPLED 256-thread groups.
// Group 0 (t<256):   stage+build x=0..3 fwd layouts,  run forward chain.
// Group 1 (t>=256):  stage+build x=4..7 adj layouts,  run adjoint chain.
// All sync = named barriers per group; one __syncthreads before the combine.
//
// u-quad layouts (row stride 76 floats):
//   group0: B0[q][r][s][u] at [ j*76 + i*4 ]  (build thread (i=s, j=r))
//           T0[q][J][I][u] at [ j*76 + i*4 ]  (i=I, j=J)
//   group1: B1[q][r][s][u] at [ i*76 + j*4 ]  (i=r, j=s)
//           T1[q][J][I][u] at [ i*76 + j*4 ]  (i=J, j=I)
// Chain step (both groups, 256 thr, thread owns (r = p>>4, I = p&15)):
//   P_u[r,I] = sum_s  B[r][s][u] * V[s,I]
//   V'[r,J=I]= sum_u sum_s T[I][s][u] * P_u[r,s]
// ---------------------------------------------------------------------------
#define XSTR 76
#define XAR  1216          // 16*76 floats per x per layout

#define SM_S    0          // 8*1024 = 8192
#define SM_B    8192       // [2 groups][4 q][1216] = 9728
#define SM_T    17920      // 9728
#define SM_P    27648      // [2][1216] = 2432
#define SM_V    30080      // [2 groups][2 buf][320] = 1280
#define SM_VF   31360      // 512
#define SM_RED  31872      // 16
#define SM_CFG  31888      // 32 ints
#define SMEM_CH (31920 * 4)

__global__ void __launch_bounds__(512, 1)
k_chain(const int* __restrict__ cfg,
        const float* __restrict__ A,
        float* __restrict__ out) {
    extern __shared__ __align__(16) float sm[];
    int* c = (int*)(sm + SM_CFG);

    const int b = blockIdx.x;
    const int t = threadIdx.x;

    if (t < 32) c[t] = cfg[b * 32 + t];
    __syncthreads();

    const __nv_bfloat16* Crow = g_Cb + b * NCOL;
    const int g = t >> 8;            // group: 0 -> x 0..3 fwd, 1 -> x 4..7 adj
    const int p = t & 255;
    const int barid = g + 1;

    float* Bg = sm + SM_B + g * 4864;    // 4*1216
    float* Tg = sm + SM_T + g * 4864;
    float* Pg = sm + SM_P + g * 1216;
    float* Vg = sm + SM_V + g * 640;

    // ---- gather A (this group's 4 x-sites) + C prefetch, all MLP ----
    float ga[16];
#pragma unroll
    for (int q = 0; q < 16; q++) {
        const int x = g * 4 + (q >> 2), y = q & 3;
        ga[q] = A[x * 2048 + y * 512 + p * 2 + c[x * 4 + y]];
    }
    uint2 rcb[4], rct[4];
#pragma unroll
    for (int q = 0; q < 4; q++) {
        const int x = g * 4 + q;
        rcb[q] = *(const uint2*)(Crow + x * 1024 + p * 4);
        rct[q] = *(const uint2*)(Crow + 8192 + x * 1024 + p * 4);
    }

#pragma unroll
    for (int q = 0; q < 16; q++) {
        const int x = g * 4 + (q >> 2), y = q & 3;
        sm[SM_S + x * 1024 + y * 256 + p] = ga[q];
    }
    asm volatile("bar.sync %0, %1;" :: "r"(barid), "r"(256) : "memory");

    // ---- builds (group's 4 x, single layout each) ----
    {
        const int i = p >> 4, j = p & 15;
        const int l = i >> 2, L = i & 3, r = j >> 2, R = j & 3;

#pragma unroll
        for (int q = 0; q < 4; q++) {
            const int x = g * 4 + q;
            const float* sb = sm + SM_S + x * 1024;

            float2 cb01 = __bfloat1622float2(*(__nv_bfloat162*)&rcb[q].x);
            float2 cb23 = __bfloat1622float2(*(__nv_bfloat162*)&rcb[q].y);
            float2 ct01 = __bfloat1622float2(*(__nv_bfloat162*)&rct[q].x);
            float2 ct23 = __bfloat1622float2(*(__nv_bfloat162*)&rct[q].y);
            const float cbv[4] = {cb01.x, cb01.y, cb23.x, cb23.y};
            const float ctv[4] = {ct01.x, ct01.y, ct23.x, ct23.y};

            float r0v[4], r3v[4];
#pragma unroll
            for (int u = 0; u < 4; u++) {
                r0v[u] = sb[l * 64 + r * 16 + u];               // s0[l,r,0,u]
                r3v[u] = sb[768 + L * 64 + R * 16 + u * 4];     // s3[L,R,u,0]
            }
            float4 b4, t4;
            {
                float v[4];
#pragma unroll
                for (int U = 0; U < 4; U++) {
                    float a0 = 0.0f;
#pragma unroll
                    for (int u = 0; u < 4; u++)
                        a0 = fmaf(r0v[u], sb[256 + L * 64 + R * 16 + u * 4 + U], a0);
                    v[U] = a0 + cbv[U];
                }
                b4 = make_float4(v[0], v[1], v[2], v[3]);
            }
            {
                float v[4];
#pragma unroll
                for (int d = 0; d < 4; d++) {
                    float a0 = 0.0f;
#pragma unroll
                    for (int u = 0; u < 4; u++)
                        a0 = fmaf(sb[512 + l * 64 + r * 16 + d * 4 + u], r3v[u], a0);
                    v[d] = a0 + ctv[d];
                }
                t4 = make_float4(v[0], v[1], v[2], v[3]);
            }
            const int off = g ? (i * XSTR + j * 4) : (j * XSTR + i * 4);
            *(float4*)(Bg + q * XAR + off) = b4;
            *(float4*)(Tg + q * XAR + off) = t4;
        }
    }

    // ---- init V, sync builds ----
    for (int q = p; q < 640; q += 256)
        Vg[q] = (q == 0) ? 1.0f : 0.0f;      // V[0,0]=1 in buffer 0
    asm volatile("bar.sync %0, %1;" :: "r"(barid), "r"(256) : "memory");

    // ---- chain: 4 steps, thread owns (r, I) ----
    const int I = p & 15;
    const int r = p >> 4;
    float aOut = 0.0f;

#pragma unroll
    for (int s4 = 0; s4 < 4; s4++) {
        const int slot = g ? (3 - s4) : s4;       // adj walks x=7..4
        const float* bx = Bg + slot * XAR;
        const float* tx = Tg + slot * XAR;
        const float* Vin  = Vg + (s4 & 1) * 320;
        float*       Vout = Vg + ((s4 + 1) & 1) * 320;

        // vl2[s] = (V[s,I], V[s,I]) packed
        unsigned long long vl2[16];
#pragma unroll
        for (int q = 0; q < 4; q++) {
            float4 v4 = *(const float4*)(Vin + I * 20 + q * 4);
            PACK2(vl2[4 * q + 0], v4.x, v4.x);
            PACK2(vl2[4 * q + 1], v4.y, v4.y);
            PACK2(vl2[4 * q + 2], v4.z, v4.z);
            PACK2(vl2[4 * q + 3], v4.w, v4.w);
        }

        // P-stage: P_u[r, I], split accumulator chains (depth 8)
        {
            unsigned long long aA0 = 0ull, aA1 = 0ull, aB0 = 0ull, aB1 = 0ull;
            const ulonglong2* bp = (const ulonglong2*)(bx + r * XSTR);
#pragma unroll
            for (int s = 0; s < 8; s++) {
                ulonglong2 q0 = bp[s], q1 = bp[s + 8];
                FMA2(aA0, q0.x, vl2[s]);
                FMA2(aA1, q1.x, vl2[s + 8]);
                FMA2(aB0, q0.y, vl2[s]);
                FMA2(aB1, q1.y, vl2[s + 8]);
            }
            float u0a, u1a, u0b, u1b, u2a, u3a, u2b, u3b;
            UNPACK2(u0a, u1a, aA0); UNPACK2(u0b, u1b, aA1);
            UNPACK2(u2a, u3a, aB0); UNPACK2(u2b, u3b, aB1);
            unsigned long long w0, w1;
            PACK2(w0, u0a + u0b, u1a + u1b);
            PACK2(w1, u2a + u2b, u3a + u3b);
            ulonglong2 pw; pw.x = w0; pw.y = w1;
            *(ulonglong2*)(Pg + r * XSTR + I * 4) = pw;
        }
        asm volatile("bar.sync %0, %1;" :: "r"(barid), "r"(256) : "memory");

        // V'-stage: V'[r, J=I] = sum_u sum_s T[I][s][u] * P_u[r, s]
        {
            unsigned long long a0p = 0ull, a1p = 0ull;
            const ulonglong2* tp = (const ulonglong2*)(tx + I * XSTR);
            const ulonglong2* pa = (const ulonglong2*)(Pg + r * XSTR);
#pragma unroll
            for (int s = 0; s < 8; s++) {
                ulonglong2 t0 = tp[s], t1 = tp[s + 8];
                ulonglong2 q0 = pa[s], q1 = pa[s + 8];
                FMA2(a0p, q0.x, t0.x);
                FMA2(a1p, q1.x, t1.x);
                FMA2(a0p, q0.y, t0.y);
                FMA2(a1p, q1.y, t1.y);
            }
            float x0, x1, y0, y1;
            UNPACK2(x0, x1, a0p);
            UNPACK2(y0, y1, a1p);
            aOut = (x0 + x1) + (y0 + y1);
            Vout[I * 20 + r] = aOut;
        }
        asm volatile("bar.sync %0, %1;" :: "r"(barid), "r"(256) : "memory");
    }

    sm[SM_VF + g * 256 + r * 16 + I] = aOut;
    __syncthreads();

    // ---- combine: dot of the two half-results ----
    if (t < 256) {
        const float* VF = sm + SM_VF;
        float prod = VF[t] * VF[256 + t];
#pragma unroll
        for (int o = 16; o; o >>= 1)
            prod += __shfl_xor_sync(0xffffffffu, prod, o);
        if ((t & 31) == 0) sm[SM_RED + (t >> 5)] = prod;
    }
    __syncthreads();
    if (t < 8) {
        float v = sm[SM_RED + t];
        v += __shfl_xor_sync(0xffu, v, 4);
        v += __shfl_xor_sync(0xffu, v, 2);
        v += __shfl_xor_sync(0xffu, v, 1);
        if (t == 0) out[b] = v;
    }
}

// ---------------------------------------------------------------------------
extern "C" void kernel_launch(void* const* d_in, const int* in_sizes, int n_in,
                              void* d_out, int out_size) {
    const int*   cfg = (const int*)d_in[0];
    const float* A   = (const float*)d_in[1];
    const float* W1  = (const float*)d_in[2];
    const float* b1  = (const float*)d_in[3];
    const float* W2  = (const float*)d_in[4];
    const float* b2  = (const float*)d_in[5];
    float* out = (float*)d_out;

    cudaFuncSetAttribute(k_chain, cudaFuncAttributeMaxDynamicSharedMemorySize,
                         SMEM_CH);

    k_gemm<<<dim3(16, 8), 512>>>(cfg, W1, b1, W2, b2);
    k_chain<<<NB, 512, SMEM_CH>>>(cfg, A, out);
}

// round 16
// speedup vs baseline: 1.1627x; 1.0125x over previous
#include <cuda_runtime.h>
#include <cuda_bf16.h>

// Problem constants: LX=8, LY=4, D=4, PHYS=2, batch=128
#define NB   128
#define NCOL 16384

// Scratch: correction matrix in bf16
__device__ __align__(16) __nv_bfloat16 g_Cb[NB * NCOL];

// f32x2 packed helpers (sm_100+ PTX)
#define FMA2(d, a, b) asm("fma.rn.f32x2 %0, %1, %2, %0;" : "+l"(d) : "l"(a), "l"(b))
#define PACK2(d, lo, hi) asm("mov.b64 %0, {%1, %2};" : "=l"(d) : "f"(lo), "f"(hi))
#define UNPACK2(lo, hi, s) asm("mov.b64 {%0, %1}, %2;" : "=f"(lo), "=f"(hi) : "l"(s))

// ---------------------------------------------------------------------------
// Kernel 1 (fused hidden + gemm), 512 thr, 2 cols x 16 batches / thread.
//   H[b,k] = relu(b1[k] + cfg[b,:]·W1[:,k])
//   C[b,n] = 0.001 * (b2[n] + H[b,:]·W2[:,n])    (bf16, paired stores)
// grid (16, 8) = 128 blocks.
// ---------------------------------------------------------------------------
__global__ void __launch_bounds__(512, 1)
k_gemm(const int* __restrict__ cfg,
       const float* __restrict__ W1,
       const float* __restrict__ b1,
       const float* __restrict__ W2,
       const float* __restrict__ b2) {
    __shared__ __align__(16) float Hs[64 * 16];   // [hidden k][batch]
    __shared__ int cs[16 * 32];                    // [batch][cfg k]

    const int tid = threadIdx.x;
    const int n0  = blockIdx.x * 1024 + tid * 2;
    const int b0  = blockIdx.y * 16;

    cs[tid] = cfg[b0 * 32 + tid];
    __syncthreads();

    {
        const int j  = tid & 63;
        const int bl = tid >> 6;          // 0..7
        float w1c[32];
#pragma unroll
        for (int k = 0; k < 32; k++) w1c[k] = W1[k * 64 + j];
        const float bj = b1[j];
        float acc0 = bj, acc1 = bj;
#pragma unroll
        for (int k = 0; k < 32; k++) {
            acc0 = fmaf((float)cs[bl * 32 + k],       w1c[k], acc0);
            acc1 = fmaf((float)cs[(bl + 8) * 32 + k], w1c[k], acc1);
        }
        Hs[j * 16 + bl]     = fmaxf(acc0, 0.0f);
        Hs[j * 16 + bl + 8] = fmaxf(acc1, 0.0f);
    }
    __syncthreads();

    unsigned long long acc0[8], acc1[8];
    {
        const float2 bb = *(const float2*)(b2 + n0);
        unsigned long long z0, z1;
        PACK2(z0, bb.x, bb.x);
        PACK2(z1, bb.y, bb.y);
#pragma unroll
        for (int p = 0; p < 8; p++) { acc0[p] = z0; acc1[p] = z1; }
    }

#pragma unroll 8
    for (int k = 0; k < 64; k++) {
        const float2 w = *(const float2*)(W2 + k * NCOL + n0);
        unsigned long long w0p, w1p;
        PACK2(w0p, w.x, w.x);
        PACK2(w1p, w.y, w.y);
        const ulonglong2* hp = (const ulonglong2*)(Hs + k * 16);
#pragma unroll
        for (int q = 0; q < 4; q++) {
            ulonglong2 hh = hp[q];
            FMA2(acc0[2 * q],     hh.x, w0p);
            FMA2(acc1[2 * q],     hh.x, w1p);
            FMA2(acc0[2 * q + 1], hh.y, w0p);
            FMA2(acc1[2 * q + 1], hh.y, w1p);
        }
    }

#pragma unroll
    for (int p = 0; p < 8; p++) {
        float l0, h0, l1, h1;
        UNPACK2(l0, h0, acc0[p]);
        UNPACK2(l1, h1, acc1[p]);
        *(__nv_bfloat162*)(g_Cb + (b0 + 2 * p)     * NCOL + n0) =
            __floats2bfloat162_rn(0.001f * l0, 0.001f * l1);
        *(__nv_bfloat162*)(g_Cb + (b0 + 2 * p + 1) * NCOL + n0) =
            __floats2bfloat162_rn(0.001f * h0, 0.001f * h1);
    }
}

// ---------------------------------------------------------------------------
// Kernel 2: assembly + split chain, two decoupled 256-thread groups.
// s2/s3 staged with last-two-dims transposed -> all build reads are LDS.128;
// bot/top accumulate in f32x2 with the bf16-C correction as accumulator init.
// V kept as duplicated f32x2 pairs (stride-18 ulonglong rows, 16B aligned).
// PDL: A-gather/staging runs pre-dependency; g_Cb reads after GridDepSync.
// ---------------------------------------------------------------------------
#define XSTR 76
#define XAR  1216          // 16*76 floats per x per layout

#define SM_S    0          // 8*1024 = 8192
#define SM_B    8192       // [2 groups][4 q][1216] = 9728
#define SM_T    17920      // 9728
#define SM_P    27648      // [2][1216] = 2432
#define SM_V2   30080      // [2 groups][2 buf][16*18] ull = 2304 floats
#define SM_VF   32384      // 512
#define SM_RED  32896      // 16
#define SM_CFG  32912      // 32 ints
#define SMEM_CH (32944 * 4)

__global__ void __launch_bounds__(512, 1)
k_chain(const int* __restrict__ cfg,
        const float* __restrict__ A,
        float* __restrict__ out) {
    extern __shared__ __align__(16) float sm[];
    int* c = (int*)(sm + SM_CFG);

    const int b = blockIdx.x;
    const int t = threadIdx.x;

    if (t < 32) c[t] = cfg[b * 32 + t];
    __syncthreads();

    const int g = t >> 8;            // group: 0 -> x 0..3 fwd, 1 -> x 4..7 adj
    const int p = t & 255;
    const int barid = g + 1;

    float* Bg = sm + SM_B + g * 4864;
    float* Tg = sm + SM_T + g * 4864;
    float* Pg = sm + SM_P + g * 1216;
    unsigned long long* V2g = (unsigned long long*)(sm + SM_V2) + g * 576;

    // ---- gather A (independent of k_gemm), stage with s2/s3 permuted ----
    float ga[16];
#pragma unroll
    for (int q = 0; q < 16; q++) {
        const int x = g * 4 + (q >> 2), y = q & 3;
        ga[q] = A[x * 2048 + y * 512 + p * 2 + c[x * 4 + y]];
    }
    {
        const int pperm = (p & ~15) | ((p & 3) << 2) | ((p >> 2) & 3);
#pragma unroll
        for (int q = 0; q < 16; q++) {
            const int x = g * 4 + (q >> 2), y = q & 3;
            sm[SM_S + x * 1024 + y * 256 + ((y < 2) ? p : pperm)] = ga[q];
        }
    }
    // init V buffer 0 (duplicated pairs): V[0,0]=1
    for (int q = p; q < 288; q += 256) {
        unsigned long long one2;
        PACK2(one2, 1.0f, 1.0f);
        V2g[q] = (q == 0) ? one2 : 0ull;
    }

    // ---- wait for k_gemm's g_Cb (PDL) ----
    cudaGridDependencySynchronize();

    const __nv_bfloat16* Crow = g_Cb + b * NCOL;
    uint2 rcb[4], rct[4];
#pragma unroll
    for (int q = 0; q < 4; q++) {
        const int x = g * 4 + q;
        rcb[q] = *(const uint2*)(Crow + x * 1024 + p * 4);
        rct[q] = *(const uint2*)(Crow + 8192 + x * 1024 + p * 4);
    }
    asm volatile("bar.sync %0, %1;" :: "r"(barid), "r"(256) : "memory");

    // ---- builds (fully vectorized: 10 LDS.128 + 16 FFMA2 per x) ----
    {
        const int i = p >> 4, j = p & 15;
        const int l = i >> 2, L = i & 3, r = j >> 2, R = j & 3;

#pragma unroll
        for (int q = 0; q < 4; q++) {
            const int x = g * 4 + q;
            const float* sb = sm + SM_S + x * 1024;

            float2 cb01 = __bfloat1622float2(*(__nv_bfloat162*)&rcb[q].x);
            float2 cb23 = __bfloat1622float2(*(__nv_bfloat162*)&rcb[q].y);
            float2 ct01 = __bfloat1622float2(*(__nv_bfloat162*)&rct[q].x);
            float2 ct23 = __bfloat1622float2(*(__nv_bfloat162*)&rct[q].y);

            float4 r0 = *(const float4*)(sb + l * 64 + r * 16);          // s0[l,r,0,:]
            float4 r3 = *(const float4*)(sb + 768 + L * 64 + R * 16);    // s3T[L,R,0,:]
            unsigned long long r0p[4], r3p[4];
            PACK2(r0p[0], r0.x, r0.x); PACK2(r0p[1], r0.y, r0.y);
            PACK2(r0p[2], r0.z, r0.z); PACK2(r0p[3], r0.w, r0.w);
            PACK2(r3p[0], r3.x, r3.x); PACK2(r3p[1], r3.y, r3.y);
            PACK2(r3p[2], r3.z, r3.z); PACK2(r3p[3], r3.w, r3.w);

            unsigned long long b01, b23, t01, t23;   // init = C correction
            PACK2(b01, cb01.x, cb01.y); PACK2(b23, cb23.x, cb23.y);
            PACK2(t01, ct01.x, ct01.y); PACK2(t23, ct23.x, ct23.y);

#pragma unroll
            for (int u = 0; u < 4; u++) {
                ulonglong2 s1q = *(const ulonglong2*)(sb + 256 + L * 64 + R * 16 + u * 4);
                ulonglong2 s2q = *(const ulonglong2*)(sb + 512 + l * 64 + r * 16 + u * 4);
                FMA2(b01, s1q.x, r0p[u]);
                FMA2(b23, s1q.y, r0p[u]);
                FMA2(t01, s2q.x, r3p[u]);
                FMA2(t23, s2q.y, r3p[u]);
            }
            const int off = g ? (i * XSTR + j * 4) : (j * XSTR + i * 4);
            ulonglong2 bq; bq.x = b01; bq.y = b23;
            ulonglong2 tq; tq.x = t01; tq.y = t23;
            *(ulonglong2*)(Bg + q * XAR + off) = bq;
            *(ulonglong2*)(Tg + q * XAR + off) = tq;
        }
    }
    asm volatile("bar.sync %0, %1;" :: "r"(barid), "r"(256) : "memory");

    // ---- chain: 4 steps, thread owns (r, I) ----
    const int I = p & 15;
    const int r = p >> 4;
    float aOut = 0.0f;

#pragma unroll
    for (int s4 = 0; s4 < 4; s4++) {
        const int slot = g ? (3 - s4) : s4;
        const float* bx = Bg + slot * XAR;
        const float* tx = Tg + slot * XAR;
        const unsigned long long* V2in = V2g + (s4 & 1) * 288;
        unsigned long long*       V2out = V2g + ((s4 + 1) & 1) * 288;

        // V column I as duplicated pairs: 8 LDS.128
        ulonglong2 vv[8];
        {
            const ulonglong2* vp = (const ulonglong2*)(V2in + I * 18);
#pragma unroll
            for (int q = 0; q < 8; q++) vv[q] = vp[q];
        }

        // P-stage: P_u[r, I] = sum_s B_u[s, r] * V[s, I]
        {
            unsigned long long aA = 0ull, aB = 0ull;
            const ulonglong2* bp = (const ulonglong2*)(bx + r * XSTR);
#pragma unroll
            for (int s = 0; s < 16; s++) {
                ulonglong2 bq = bp[s];
                unsigned long long vl = (s & 1) ? vv[s >> 1].y : vv[s >> 1].x;
                FMA2(aA, bq.x, vl);
                FMA2(aB, bq.y, vl);
            }
            ulonglong2 pw; pw.x = aA; pw.y = aB;
            *(ulonglong2*)(Pg + r * XSTR + I * 4) = pw;
        }
        asm volatile("bar.sync %0, %1;" :: "r"(barid), "r"(256) : "memory");

        // V'-stage: V'[r, J=I] = sum_u sum_s P_u[r, s] * T_u[s, J]
        {
            unsigned long long a01 = 0ull, a23 = 0ull;
            const ulonglong2* tp = (const ulonglong2*)(tx + I * XSTR);
            const ulonglong2* pp = (const ulonglong2*)(Pg + r * XSTR);
#pragma unroll
            for (int s = 0; s < 16; s++) {
                ulonglong2 tq = tp[s];
                ulonglong2 pq = pp[s];
                FMA2(a01, pq.x, tq.x);
                FMA2(a23, pq.y, tq.y);
            }
            float x0, x1, y0, y1;
            UNPACK2(x0, x1, a01);
            UNPACK2(y0, y1, a23);
            aOut = (x0 + x1) + (y0 + y1);
        }
        if (s4 < 3) {
            unsigned long long av;
            PACK2(av, aOut, aOut);
            V2out[I * 18 + r] = av;
            asm volatile("bar.sync %0, %1;" :: "r"(barid), "r"(256) : "memory");
        }
    }

    sm[SM_VF + g * 256 + r * 16 + I] = aOut;
    __syncthreads();

    // ---- combine: dot of the two half-results ----
    if (t < 256) {
        const float* VF = sm + SM_VF;
        float prod = VF[t] * VF[256 + t];
#pragma unroll
        for (int o = 16; o; o >>= 1)
            prod += __shfl_xor_sync(0xffffffffu, prod, o);
        if ((t & 31) == 0) sm[SM_RED + (t >> 5)] = prod;
    }
    __syncthreads();
    if (t < 8) {
        float v = sm[SM_RED + t];
        v += __shfl_xor_sync(0xffu, v, 4);
        v += __shfl_xor_sync(0xffu, v, 2);
        v += __shfl_xor_sync(0xffu, v, 1);
        if (t == 0) out[b] = v;
    }
}

// ---------------------------------------------------------------------------
extern "C" void kernel_launch(void* const* d_in, const int* in_sizes, int n_in,
                              void* d_out, int out_size) {
    const int*   cfg = (const int*)d_in[0];
    const float* A   = (const float*)d_in[1];
    const float* W1  = (const float*)d_in[2];
    const float* b1  = (const float*)d_in[3];
    const float* W2  = (const float*)d_in[4];
    const float* b2  = (const float*)d_in[5];
    float* out = (float*)d_out;

    cudaFuncSetAttribute(k_chain, cudaFuncAttributeMaxDynamicSharedMemorySize,
                         SMEM_CH);

    k_gemm<<<dim3(16, 8), 512>>>(cfg, W1, b1, W2, b2);

    // k_chain with PDL (programmatic stream serialization); fallback = plain.
    cudaLaunchConfig_t cfg2 = {};
    cfg2.gridDim  = dim3(NB, 1, 1);
    cfg2.blockDim = dim3(512, 1, 1);
    cfg2.dynamicSmemBytes = SMEM_CH;
    cfg2.stream = 0;
    cudaLaunchAttribute at[1];
    at[0].id = cudaLaunchAttributeProgrammaticStreamSerialization;
    at[0].val.programmaticStreamSerializationAllowed = 1;
    cfg2.attrs = at;
    cfg2.numAttrs = 1;
    cudaError_t e = cudaLaunchKernelEx(&cfg2, k_chain, cfg, A, out);
    if (e != cudaSuccess) {
        cudaGetLastError();   // clear
        k_chain<<<NB, 512, SMEM_CH>>>(cfg, A, out);
    }
}